// round 11
// baseline (speedup 1.0000x reference)
#include <cuda_runtime.h>
#include <cuda_fp16.h>
#include <stdint.h>

// DayAdapter via fp16 mma.sync m16n8k16: y = softsign(x + xh@Eh + b),
// E = W - I. Eh kept in W-native [day][k][n] layout (prep = streaming convert,
// no transpose); B fragments loaded with ldmatrix.x4.trans in the main loop.
// 4-stage mbarrier cp.async pipeline, 2 CTAs/SM.

#define DIMK 512
#define TOK  1024
#define NB   64
#define NDAYS 24

#define CTA_M 128
#define CTA_N 128
#define BK    32
#define KSTEPS (DIMK / BK)       // 16
#define NTHREADS 256             // 8 warps: 2(m) x 4(n), warp tile 64x32
#define STAGES 4

#define SM_TILES 128             // mbarriers live in [0,128)
#define STG_BYTES 16384          // A 8KB (128 rows x 64B) | B 8KB (32 rows x 256B)
#define OFF_A 0
#define OFF_B 8192
#define SMEM_TOTAL (SM_TILES + STAGES * STG_BYTES)   // 65664

__device__ __half g_xh[(size_t)NB * TOK * DIMK];       // fp16(x)
__device__ __half g_Eh[(size_t)NDAYS * DIMK * DIMK];   // fp16(W - I), [day][k][n]

// ---------------- helpers ----------------
__device__ __forceinline__ uint32_t smem_u32(const void* p) {
    return (uint32_t)__cvta_generic_to_shared(p);
}
// A tile: 64B rows, 4 chunks of 16B
__device__ __forceinline__ uint32_t swz64(uint32_t row, uint32_t ch) {
    return row * 64u + ((ch ^ ((row >> 1) & 3u)) << 4);
}
// B tile: 256B rows, 16 chunks of 16B; low 3 chunk bits xor row&7
__device__ __forceinline__ uint32_t swz256(uint32_t row, uint32_t ch) {
    return row * 256u + ((ch ^ (row & 7u)) << 4);
}
__device__ __forceinline__ void ldsm_x4(uint32_t* r, uint32_t addr) {
    asm volatile("ldmatrix.sync.aligned.m8n8.x4.shared.b16 {%0,%1,%2,%3}, [%4];"
                 : "=r"(r[0]), "=r"(r[1]), "=r"(r[2]), "=r"(r[3]) : "r"(addr));
}
__device__ __forceinline__ void ldsm_x4_t(uint32_t* r, uint32_t addr) {
    asm volatile("ldmatrix.sync.aligned.m8n8.x4.trans.shared.b16 {%0,%1,%2,%3}, [%4];"
                 : "=r"(r[0]), "=r"(r[1]), "=r"(r[2]), "=r"(r[3]) : "r"(addr));
}
__device__ __forceinline__ void mma_f16(float* c, const uint32_t* a, uint32_t b0, uint32_t b1) {
    asm volatile(
        "mma.sync.aligned.m16n8k16.row.col.f32.f16.f16.f32 "
        "{%0,%1,%2,%3}, {%4,%5,%6,%7}, {%8,%9}, {%0,%1,%2,%3};"
        : "+f"(c[0]), "+f"(c[1]), "+f"(c[2]), "+f"(c[3])
        : "r"(a[0]), "r"(a[1]), "r"(a[2]), "r"(a[3]), "r"(b0), "r"(b1));
}
__device__ __forceinline__ void cp_async16(uint32_t dst, const void* src) {
    asm volatile("cp.async.cg.shared.global [%0], [%1], 16;" :: "r"(dst), "l"(src));
}
__device__ __forceinline__ void cp_mbar_arrive(uint32_t mbar) {
    asm volatile("cp.async.mbarrier.arrive.noinc.shared.b64 [%0];" :: "r"(mbar) : "memory");
}
__device__ __forceinline__ void mbar_init(uint32_t addr, uint32_t cnt) {
    asm volatile("mbarrier.init.shared.b64 [%0], %1;" :: "r"(addr), "r"(cnt) : "memory");
}
__device__ __forceinline__ void mbar_arrive(uint32_t addr) {
    asm volatile("mbarrier.arrive.shared.b64 _, [%0];" :: "r"(addr) : "memory");
}
__device__ __forceinline__ void mbar_wait(uint32_t addr, uint32_t parity) {
    asm volatile(
        "{\n\t.reg .pred P;\n"
        "W%=:\n\t"
        "mbarrier.try_wait.parity.acquire.cta.shared::cta.b64 P, [%0], %1, 0x989680;\n\t"
        "@!P bra W%=;\n\t}"
        :: "r"(addr), "r"(parity) : "memory");
}

// ---------------- prep kernels (both pure streaming) ----------------
// Eh[d][k][n] = fp16(W[d][k][n] - (k==n)); flat layout identical to W
__global__ void __launch_bounds__(256, 8) prep_e_kernel(const float* __restrict__ W) {
    const size_t i = (size_t)blockIdx.x * blockDim.x + threadIdx.x;   // float4 index
    const size_t e = i * 4;                                           // element index
    float4 v = __ldg((const float4*)W + i);
    const int r = (int)(e & (DIMK * DIMK - 1));                       // index within day
    const int k = r >> 9;
    const int n = r & (DIMK - 1);
    const int dlt = k - n;                                            // diag if 0..3
    if (dlt == 0) v.x -= 1.0f;
    else if (dlt == 1) v.y -= 1.0f;
    else if (dlt == 2) v.z -= 1.0f;
    else if (dlt == 3) v.w -= 1.0f;
    __half2 h0 = __float22half2_rn(make_float2(v.x, v.y));
    __half2 h1 = __float22half2_rn(make_float2(v.z, v.w));
    uint2 o;
    o.x = *(uint32_t*)&h0;
    o.y = *(uint32_t*)&h1;
    ((uint2*)g_Eh)[i] = o;
}

// xh = fp16(x)
__global__ void __launch_bounds__(256, 8) prep_x_kernel(const float* __restrict__ x) {
    const size_t i = (size_t)blockIdx.x * blockDim.x + threadIdx.x;   // float4 index
    const float4 v = __ldg((const float4*)x + i);
    __half2 h0 = __float22half2_rn(make_float2(v.x, v.y));
    __half2 h1 = __float22half2_rn(make_float2(v.z, v.w));
    uint2 o;
    o.x = *(uint32_t*)&h0;
    o.y = *(uint32_t*)&h1;
    ((uint2*)g_xh)[i] = o;
}

// ---------------- main ----------------
__global__ void __launch_bounds__(NTHREADS, 2)
day_adapter_f16(const float* __restrict__ x,
                const int*   __restrict__ day_w,
                const float* __restrict__ bias,
                float*       __restrict__ out)
{
    extern __shared__ char smem[];
    const uint32_t sb = smem_u32(smem);
    const int tid  = threadIdx.x;
    const int wid  = tid >> 5;
    const int lane = tid & 31;

    const int n0   = blockIdx.x * CTA_N;
    const int m0   = blockIdx.y * CTA_M;
    const int bidx = blockIdx.z;

    const uint32_t mb_full  = sb;        // full[i] at sb + i*8
    const uint32_t mb_empty = sb + 64;   // empty[i] at sb + 64 + i*8
    if (tid == 0) {
        #pragma unroll
        for (int i = 0; i < STAGES; i++) {
            mbar_init(mb_full  + i * 8, NTHREADS);
            mbar_init(mb_empty + i * 8, NTHREADS);
        }
    }

    // robust day_ids decode (int32 vs int64 buffer)
    int is64 = 1;
    #pragma unroll 8
    for (int i = 1; i < 64; i += 2)
        if (__ldg(day_w + i) != 0) is64 = 0;
    const int day = is64 ? __ldg(day_w + 2 * bidx) : __ldg(day_w + bidx);

    __syncthreads();   // mbarrier init visible before any arrivals

    // -------- stage loaders --------
    // A: thread t -> row=t>>1 (128 rows), chunks (t&1)*2, +1
    const int arow = tid >> 1;
    const int ac0  = (tid & 1) * 2;
    const __half* agp = g_xh + ((size_t)bidx * TOK + m0 + arow) * DIMK + ac0 * 8;
    const uint32_t aso0 = swz64(arow, ac0), aso1 = swz64(arow, ac0 + 1);
    // B: thread t -> row = t&31 (32 k-rows), chunks wid*2, +1 (conflict-free phases)
    const int brow = tid & 31;
    const int bc0  = (tid >> 5) * 2;
    const __half* bgp = g_Eh + ((size_t)day * DIMK + brow) * DIMK + n0 + bc0 * 8;
    const uint32_t bso0 = swz256(brow, bc0), bso1 = swz256(brow, bc0 + 1);

    auto LOAD_STAGE = [&](uint32_t stg, int s) {
        const __half* asrc = agp + s * BK;
        const __half* bsrc = bgp + (size_t)s * BK * DIMK;   // advance 32 k-rows
        cp_async16(stg + OFF_A + aso0, asrc);
        cp_async16(stg + OFF_A + aso1, asrc + 8);
        cp_async16(stg + OFF_B + bso0, bsrc);
        cp_async16(stg + OFF_B + bso1, bsrc + 8);
    };

    // -------- warp tile: 2(m) x 4(n), 64x32 --------
    const int mw = (wid >> 2) * 64;
    const int nw = (wid & 3) * 32;
    const int kswap = wid & 1;               // odd warps traverse kg as 1,0

    float acc[4][4][4];
    #pragma unroll
    for (int i = 0; i < 4; i++)
        #pragma unroll
        for (int j = 0; j < 4; j++)
            #pragma unroll
            for (int q = 0; q < 4; q++) acc[i][j][q] = 0.0f;

    // A ldmatrix lane addressing (64B rows)
    const int a_row = mw + (lane & 15);                       // + mt*16
    const int a_ch  = lane >> 4;                              // + 2*kg
    // B trans-ldmatrix lane addressing (256B rows, [k][n]):
    // matrix g = lane>>3: g0=(k+0..7, n+0..7)->b0 even, g1=(k+8..15, n0..7)->b1 even,
    // g2=(k0..7, n+8..15)->b0 odd, g3=(k8..15, n8..15)->b1 odd
    const int bt_g   = lane >> 3;
    const int bt_row = (lane & 7) + ((bt_g & 1) << 3);        // + kg*16
    const int bt_ch  = (nw >> 3) + (bt_g >> 1);               // + p*2

    // -------- prolog: fill slots 0..2 --------
    LOAD_STAGE(sb + SM_TILES + 0 * STG_BYTES, 0);
    cp_mbar_arrive(mb_full + 0 * 8);
    LOAD_STAGE(sb + SM_TILES + 1 * STG_BYTES, 1);
    cp_mbar_arrive(mb_full + 1 * 8);
    LOAD_STAGE(sb + SM_TILES + 2 * STG_BYTES, 2);
    cp_mbar_arrive(mb_full + 2 * 8);

    int slotC = 0;
    int slotP = STAGES - 1;
    uint32_t phF = 0, phE = 0;

    // -------- main loop: mbarrier-paced, no CTA barrier --------
    #pragma unroll 1
    for (int s = 0; s < KSTEPS; s++) {
        const uint32_t stg  = sb + SM_TILES + slotC * STG_BYTES;
        const uint32_t stgA = stg + OFF_A;
        const uint32_t stgB = stg + OFF_B;

        mbar_wait(mb_full + slotC * 8, (phF >> slotC) & 1);
        phF ^= 1u << slotC;

        // fragment double buffers; preload first kg (= kswap)
        uint32_t bf[2][8];
        uint32_t af[2][4];
        ldsm_x4_t(bf[0] + 0, stgB + swz256(kswap * 16 + bt_row, bt_ch));
        ldsm_x4_t(bf[0] + 4, stgB + swz256(kswap * 16 + bt_row, bt_ch + 2));
        ldsm_x4(af[0], stgA + swz64(a_row, 2 * kswap + a_ch));

        // producer: refill slotP for stage s+3
        if (s + STAGES - 1 < KSTEPS) {
            if (s > 0) {
                mbar_wait(mb_empty + slotP * 8, (phE >> slotP) & 1);
                phE ^= 1u << slotP;
            }
            LOAD_STAGE(sb + SM_TILES + slotP * STG_BYTES, s + STAGES - 1);
            cp_mbar_arrive(mb_full + slotP * 8);
        }

        int ab = 0;
        #pragma unroll
        for (int kg = 0; kg < 2; kg++) {
            const int cur = kg;
            const int kk  = kg ^ kswap;
            const int kkn = kk ^ 1;             // the other kg
            if (kg < 1) {
                ldsm_x4_t(bf[1] + 0, stgB + swz256(kkn * 16 + bt_row, bt_ch));
                ldsm_x4_t(bf[1] + 4, stgB + swz256(kkn * 16 + bt_row, bt_ch + 2));
            }
            #pragma unroll
            for (int mt = 0; mt < 4; mt++) {
                if (mt < 3)
                    ldsm_x4(af[ab ^ 1], stgA + swz64(a_row + (mt + 1) * 16, 2 * kk + a_ch));
                else if (kg < 1)
                    ldsm_x4(af[ab ^ 1], stgA + swz64(a_row, 2 * kkn + a_ch));
                #pragma unroll
                for (int nt = 0; nt < 4; nt++)
                    mma_f16(acc[mt][nt], af[ab],
                            bf[cur][(nt >> 1) * 4 + (nt & 1) * 2],
                            bf[cur][(nt >> 1) * 4 + (nt & 1) * 2 + 1]);
                ab ^= 1;
            }
        }

        mbar_arrive(mb_empty + slotC * 8);

        slotC = (slotC == STAGES - 1) ? 0 : slotC + 1;
        slotP = (slotP == STAGES - 1) ? 0 : slotP + 1;
    }

    // -------- epilogue: y = x (exact fp32) + acc + bias; softsign --------
    const int r  = lane >> 2;
    const int cq = (lane & 3) * 2;
    const float* xep = x + (size_t)bidx * TOK * DIMK;
    const float* bp  = bias + (size_t)day * DIMK;

    #pragma unroll
    for (int nt = 0; nt < 4; nt++) {
        const int n = n0 + nw + nt * 8 + cq;
        const float2 bb = *(const float2*)(bp + n);
        #pragma unroll
        for (int mt = 0; mt < 4; mt++) {
            const int m = m0 + mw + mt * 16 + r;
            const float2 x0 = __ldg((const float2*)(xep + (size_t)m * DIMK + n));
            const float2 x1 = __ldg((const float2*)(xep + (size_t)(m + 8) * DIMK + n));
            float y0 = acc[mt][nt][0] + x0.x + bb.x;
            float y1 = acc[mt][nt][1] + x0.y + bb.y;
            float y2 = acc[mt][nt][2] + x1.x + bb.x;
            float y3 = acc[mt][nt][3] + x1.y + bb.y;
            float2 o0, o1;
            o0.x = __fdividef(y0, 1.0f + fabsf(y0));
            o0.y = __fdividef(y1, 1.0f + fabsf(y1));
            o1.x = __fdividef(y2, 1.0f + fabsf(y2));
            o1.y = __fdividef(y3, 1.0f + fabsf(y3));
            *(float2*)(out + (size_t)bidx * TOK * DIMK + (size_t)m * DIMK + n)       = o0;
            *(float2*)(out + (size_t)bidx * TOK * DIMK + (size_t)(m + 8) * DIMK + n) = o1;
        }
    }
}

// ---------------- launch ----------------
extern "C" void kernel_launch(void* const* d_in, const int* in_sizes, int n_in,
                              void* d_out, int out_size)
{
    const float* x   = (const float*)d_in[0];
    const int*   day = (const int*)  d_in[1];
    const float* W   = (const float*)d_in[2];
    const float* b   = (const float*)d_in[3];
    float*       out = (float*)d_out;

    cudaFuncSetAttribute(day_adapter_f16,
                         cudaFuncAttributeMaxDynamicSharedMemorySize, SMEM_TOTAL);

    const size_t ne4 = (size_t)NDAYS * DIMK * DIMK / 4;   // 1572864
    prep_e_kernel<<<(unsigned)(ne4 / 256), 256>>>(W);

    const size_t nx4 = (size_t)NB * TOK * DIMK / 4;       // 8388608
    prep_x_kernel<<<(unsigned)(nx4 / 256), 256>>>(x);

    dim3 grid(DIMK / CTA_N, TOK / CTA_M, NB);   // (4, 8, 64) = 2048 CTAs
    day_adapter_f16<<<grid, NTHREADS, SMEM_TOTAL>>>(x, day, b, out);
}